// round 1
// baseline (speedup 1.0000x reference)
#include <cuda_runtime.h>
#include <math.h>

#define IN_DIM 4096
#define HDIM   2048
#define NPTS   2097152

// Scratch (allocation-free): __device__ globals.
__device__ float g_A [IN_DIM * HDIM];   // tanh(W1 + b1)      32 MB
__device__ float g_H2[IN_DIM * HDIM];   // tanh(A@W2 + b2)    32 MB
__device__ float g_u [IN_DIM];          // 3*tanh(H2@W3 + b3) 16 KB (64x64 grid)

// ---------------------------------------------------------------------------
// Kernel 0: A = tanh(W1 + b1)   (row-broadcast of b1 over 4096 rows)
// ---------------------------------------------------------------------------
__global__ void prep_A_kernel(const float* __restrict__ W1,
                              const float* __restrict__ b1) {
    int i = blockIdx.x * blockDim.x + threadIdx.x;     // float4 index
    if (i >= (IN_DIM * HDIM) / 4) return;
    float4 w = reinterpret_cast<const float4*>(W1)[i];
    float4 b = reinterpret_cast<const float4*>(b1)[i & (HDIM / 4 - 1)];
    float4 r;
    r.x = tanhf(w.x + b.x);
    r.y = tanhf(w.y + b.y);
    r.z = tanhf(w.z + b.z);
    r.w = tanhf(w.w + b.w);
    reinterpret_cast<float4*>(g_A)[i] = r;
}

// ---------------------------------------------------------------------------
// Kernel 1: H2 = tanh(A @ W2 + b2)
// 128x128 tile, BK=16, 256 threads, 8x8 per-thread register tile.
// ---------------------------------------------------------------------------
#define BM 128
#define BN 128
#define BK 16
#define TM 8
#define TN 8

__global__ __launch_bounds__(256, 2)
void gemm_tanh_kernel(const float* __restrict__ B,    // W2: HDIM x HDIM
                      const float* __restrict__ b2) { // HDIM
    __shared__ float As[BK][BM];   // A tile stored transposed (k-major)
    __shared__ float Bs[BK][BN];

    const float* A = g_A;
    float*       C = g_H2;

    const int bn  = blockIdx.x;        // 0..15  (N tiles)
    const int bm  = blockIdx.y;        // 0..31  (M tiles)
    const int tid = threadIdx.x;
    const int tr  = tid >> 4;          // 0..15  row group
    const int tc  = tid & 15;          // 0..15  col group

    float acc[TM][TN];
#pragma unroll
    for (int i = 0; i < TM; i++)
#pragma unroll
        for (int j = 0; j < TN; j++) acc[i][j] = 0.0f;

    for (int k0 = 0; k0 < HDIM; k0 += BK) {
        // --- load A tile (128 rows x 16 k) as float4 along K, store transposed
#pragma unroll
        for (int l = 0; l < 2; l++) {
            int idx  = l * 256 + tid;        // 0..511
            int row  = idx >> 2;             // 0..127
            int c4   = idx & 3;              // 0..3 (float4 within the 16 k)
            float4 v = *reinterpret_cast<const float4*>(
                &A[(size_t)(bm * BM + row) * HDIM + k0 + c4 * 4]);
            As[c4 * 4 + 0][row] = v.x;
            As[c4 * 4 + 1][row] = v.y;
            As[c4 * 4 + 2][row] = v.z;
            As[c4 * 4 + 3][row] = v.w;
        }
        // --- load B tile (16 k x 128 cols) as float4 along N
#pragma unroll
        for (int l = 0; l < 2; l++) {
            int idx  = l * 256 + tid;        // 0..511
            int row  = idx >> 5;             // 0..15
            int c4   = idx & 31;             // 0..31
            float4 v = *reinterpret_cast<const float4*>(
                &B[(size_t)(k0 + row) * HDIM + bn * BN + c4 * 4]);
            *reinterpret_cast<float4*>(&Bs[row][c4 * 4]) = v;
        }
        __syncthreads();

#pragma unroll
        for (int kk = 0; kk < BK; kk++) {
            float a[TM], b[TN];
            float4 a0 = *reinterpret_cast<const float4*>(&As[kk][tr * TM]);
            float4 a1 = *reinterpret_cast<const float4*>(&As[kk][tr * TM + 4]);
            a[0]=a0.x; a[1]=a0.y; a[2]=a0.z; a[3]=a0.w;
            a[4]=a1.x; a[5]=a1.y; a[6]=a1.z; a[7]=a1.w;
            float4 b0 = *reinterpret_cast<const float4*>(&Bs[kk][tc * TN]);
            float4 b1v= *reinterpret_cast<const float4*>(&Bs[kk][tc * TN + 4]);
            b[0]=b0.x; b[1]=b0.y; b[2]=b0.z; b[3]=b0.w;
            b[4]=b1v.x; b[5]=b1v.y; b[6]=b1v.z; b[7]=b1v.w;
#pragma unroll
            for (int i = 0; i < TM; i++)
#pragma unroll
                for (int j = 0; j < TN; j++)
                    acc[i][j] = fmaf(a[i], b[j], acc[i][j]);
        }
        __syncthreads();
    }

    // --- epilogue: + b2, tanh, store
    const int crow = bm * BM + tr * TM;
    const int ccol = bn * BN + tc * TN;
    float4 bias0 = *reinterpret_cast<const float4*>(&b2[ccol]);
    float4 bias1 = *reinterpret_cast<const float4*>(&b2[ccol + 4]);
    float bias[TN] = {bias0.x, bias0.y, bias0.z, bias0.w,
                      bias1.x, bias1.y, bias1.z, bias1.w};
#pragma unroll
    for (int i = 0; i < TM; i++) {
        float4 o0, o1;
        o0.x = tanhf(acc[i][0] + bias[0]);
        o0.y = tanhf(acc[i][1] + bias[1]);
        o0.z = tanhf(acc[i][2] + bias[2]);
        o0.w = tanhf(acc[i][3] + bias[3]);
        o1.x = tanhf(acc[i][4] + bias[4]);
        o1.y = tanhf(acc[i][5] + bias[5]);
        o1.z = tanhf(acc[i][6] + bias[6]);
        o1.w = tanhf(acc[i][7] + bias[7]);
        *reinterpret_cast<float4*>(&C[(size_t)(crow + i) * HDIM + ccol])     = o0;
        *reinterpret_cast<float4*>(&C[(size_t)(crow + i) * HDIM + ccol + 4]) = o1;
    }
}

// ---------------------------------------------------------------------------
// Kernel 2: u = 3 * tanh(H2 @ W3 + b3)   (one warp per row)
// ---------------------------------------------------------------------------
__global__ void gemv_tanh_kernel(const float* __restrict__ W3,
                                 const float* __restrict__ b3) {
    int row  = blockIdx.x * 8 + (threadIdx.x >> 5);   // 8 warps per block
    int lane = threadIdx.x & 31;
    const float4* r = reinterpret_cast<const float4*>(g_H2 + (size_t)row * HDIM);
    const float4* w = reinterpret_cast<const float4*>(W3);
    float s = 0.0f;
#pragma unroll 4
    for (int j = lane; j < HDIM / 4; j += 32) {
        float4 a = r[j], b = w[j];
        s += a.x * b.x + a.y * b.y + a.z * b.z + a.w * b.w;
    }
#pragma unroll
    for (int o = 16; o > 0; o >>= 1) s += __shfl_down_sync(0xffffffffu, s, o);
    if (lane == 0) g_u[row] = tanhf(s + b3[0]) * 3.0f;
}

// ---------------------------------------------------------------------------
// Kernel 3: spline evaluation over 2M points against 64x64 grid in SMEM
// ---------------------------------------------------------------------------
__global__ __launch_bounds__(256)
void spline_kernel(const float2* __restrict__ pts, float* __restrict__ out) {
    __shared__ float su[64 * 64];
    for (int i = threadIdx.x; i < 64 * 64; i += 256) su[i] = g_u[i];
    __syncthreads();

    for (int idx = blockIdx.x * blockDim.x + threadIdx.x; idx < NPTS;
         idx += gridDim.x * blockDim.x) {
        float2 p = pts[idx];
        float x = (p.x + 1.0f) * 0.5f;
        float y = p.y;

        float pfx = x * 62.0f;
        float flx = floorf(pfx);
        int   posx = min((int)flx + 1, 62);
        float tx = pfx - flx;
        float omtx = 1.0f - tx;
        float bx0 = 0.5f * omtx * omtx;
        float bx1 = -tx * tx + tx + 0.5f;
        float bx2 = 0.5f * tx * tx;

        float pfy = y * 62.0f;
        float fly = floorf(pfy);
        int   posy = min((int)fly + 1, 62);
        float ty = pfy - fly;
        float omty = 1.0f - ty;
        float by0 = 0.5f * omty * omty;
        float by1 = -ty * ty + ty + 0.5f;
        float by2 = 0.5f * ty * ty;

        const float* base = su + (posx - 1) * 64 + (posy - 1);
        float r0 = base[  0] * by0 + base[  1] * by1 + base[  2] * by2;
        float r1 = base[ 64] * by0 + base[ 65] * by1 + base[ 66] * by2;
        float r2 = base[128] * by0 + base[129] * by1 + base[130] * by2;
        out[idx] = r0 * bx0 + r1 * bx1 + r2 * bx2;
    }
}

// ---------------------------------------------------------------------------
// Launch
// ---------------------------------------------------------------------------
extern "C" void kernel_launch(void* const* d_in, const int* in_sizes, int n_in,
                              void* d_out, int out_size) {
    const float* points = (const float*)d_in[0];   // (NPTS, 2)
    const float* W1     = (const float*)d_in[1];   // (4096, 2048)
    const float* b1     = (const float*)d_in[2];   // (2048,)
    const float* W2     = (const float*)d_in[3];   // (2048, 2048)
    const float* b2     = (const float*)d_in[4];   // (2048,)
    const float* W3     = (const float*)d_in[5];   // (2048, 1)
    const float* b3     = (const float*)d_in[6];   // (1,)
    float* out = (float*)d_out;

    // 0: A = tanh(W1 + b1)
    {
        int n4 = (IN_DIM * HDIM) / 4;
        prep_A_kernel<<<(n4 + 255) / 256, 256>>>(W1, b1);
    }
    // 1: H2 = tanh(A @ W2 + b2)
    {
        dim3 grid(HDIM / BN, IN_DIM / BM);
        gemm_tanh_kernel<<<grid, 256>>>(W2, b2);
    }
    // 2: u = 3 * tanh(H2 @ W3 + b3)
    gemv_tanh_kernel<<<IN_DIM / 8, 256>>>(W3, b3);
    // 3: spline
    spline_kernel<<<4096, 256>>>((const float2*)points, out);
}

// round 3
// speedup vs baseline: 2.6950x; 2.6950x over previous
#include <cuda_runtime.h>
#include <math.h>
#include <stdint.h>

#define IN_DIM 4096
#define HDIM   2048
#define NPTS   2097152

// Scratch (allocation-free): __device__ globals.
__device__ float g_A [IN_DIM * HDIM];   // tanh(W1 + b1), tf32-rounded   32 MB
__device__ float g_Bt[HDIM * HDIM];     // W2^T (N-major rows), tf32     16 MB
__device__ float g_H2[IN_DIM * HDIM];   // tanh(A@W2 + b2)               32 MB
__device__ float g_u [IN_DIM];          // 3*tanh(H2@W3 + b3) (64x64 grid)

__device__ __forceinline__ float tf32_rn(float x) {
    uint32_t u;
    asm("cvt.rna.tf32.f32 %0, %1;" : "=r"(u) : "f"(x));
    return __uint_as_float(u);
}

#define CP_ASYNC16(dst, src) \
    asm volatile("cp.async.cg.shared.global [%0], [%1], 16;" \
                 :: "r"(dst), "l"(src) : "memory")
#define CP_COMMIT()  asm volatile("cp.async.commit_group;" ::: "memory")
#define CP_WAIT2()   asm volatile("cp.async.wait_group 2;" ::: "memory")

__device__ __forceinline__ void mma_tf32(float* d, const float* a, const float* b) {
    asm volatile(
        "mma.sync.aligned.m16n8k8.row.col.f32.tf32.tf32.f32 "
        "{%0,%1,%2,%3}, {%4,%5,%6,%7}, {%8,%9}, {%0,%1,%2,%3};"
        : "+f"(d[0]), "+f"(d[1]), "+f"(d[2]), "+f"(d[3])
        : "r"(__float_as_uint(a[0])), "r"(__float_as_uint(a[1])),
          "r"(__float_as_uint(a[2])), "r"(__float_as_uint(a[3])),
          "r"(__float_as_uint(b[0])), "r"(__float_as_uint(b[1])));
}

// ---------------------------------------------------------------------------
// Kernel 0: A = tf32_rn(tanh(W1 + b1))
// ---------------------------------------------------------------------------
__global__ void prep_A_kernel(const float* __restrict__ W1,
                              const float* __restrict__ b1) {
    int i = blockIdx.x * blockDim.x + threadIdx.x;
    if (i >= (IN_DIM * HDIM) / 4) return;
    float4 w = reinterpret_cast<const float4*>(W1)[i];
    float4 b = reinterpret_cast<const float4*>(b1)[i & (HDIM / 4 - 1)];
    float4 r;
    r.x = tf32_rn(tanhf(w.x + b.x));
    r.y = tf32_rn(tanhf(w.y + b.y));
    r.z = tf32_rn(tanhf(w.z + b.z));
    r.w = tf32_rn(tanhf(w.w + b.w));
    reinterpret_cast<float4*>(g_A)[i] = r;
}

// ---------------------------------------------------------------------------
// Kernel 0b: g_Bt[n][k] = tf32_rn(W2[k][n])
// ---------------------------------------------------------------------------
__global__ void transpose_kernel(const float* __restrict__ W2) {
    __shared__ float t[32][33];
    int bx = blockIdx.x, by = blockIdx.y;
    int tx = threadIdx.x, ty = threadIdx.y;      // (32, 8)
#pragma unroll
    for (int i = 0; i < 32; i += 8)
        t[ty + i][tx] = tf32_rn(W2[(size_t)(by * 32 + ty + i) * HDIM + bx * 32 + tx]);
    __syncthreads();
#pragma unroll
    for (int i = 0; i < 32; i += 8)
        g_Bt[(size_t)(bx * 32 + ty + i) * HDIM + by * 32 + tx] = t[tx][ty + i];
}

// ---------------------------------------------------------------------------
// Kernel 1: H2 = tanh(A @ W2 + b2)
//   mma.sync m16n8k8 tf32, CTA tile 128x128, BK=32, 4-stage cp.async pipe.
//   8 warps (2 M x 4 N), warp tile 64x32 -> 4x4 mma tiles.
// ---------------------------------------------------------------------------
#define ASTR 36                         // floats per smem row (32 + 4 pad)
#define STAGE_FLOATS (2 * 128 * ASTR)   // A tile + B tile = 9216 floats
#define NSTAGE 4
#define GEMM_SMEM (NSTAGE * STAGE_FLOATS * 4)  // 147456 bytes

__device__ __forceinline__ void load_stage(float* sm, int kt, int bm, int bn, int tid) {
    float* As = sm;
    float* Bs = sm + 128 * ASTR;
    const int k0 = kt * 32;
#pragma unroll
    for (int i = 0; i < 4; i++) {
        int g = i * 256 + tid;          // 0..1023
        int row = g >> 3, c16 = g & 7;
        uint32_t da = (uint32_t)__cvta_generic_to_shared(As + row * ASTR + c16 * 4);
        const float* sa = g_A + (size_t)(bm * 128 + row) * HDIM + k0 + c16 * 4;
        CP_ASYNC16(da, sa);
    }
#pragma unroll
    for (int i = 0; i < 4; i++) {
        int g = i * 256 + tid;
        int row = g >> 3, c16 = g & 7;
        uint32_t db = (uint32_t)__cvta_generic_to_shared(Bs + row * ASTR + c16 * 4);
        const float* sb = g_Bt + (size_t)(bn * 128 + row) * HDIM + k0 + c16 * 4;
        CP_ASYNC16(db, sb);
    }
    CP_COMMIT();
}

__global__ __launch_bounds__(256, 1)
void gemm_mma_kernel(const float* __restrict__ b2) {
    extern __shared__ float sm[];
    const int tid  = threadIdx.x;
    const int lane = tid & 31, wid = tid >> 5;
    const int warpM = wid & 1;          // 0..1
    const int warpN = wid >> 1;         // 0..3
    const int bm = blockIdx.y, bn = blockIdx.x;
    const int r = lane >> 2, c = lane & 3;

    float acc[4][4][4];
#pragma unroll
    for (int i = 0; i < 4; i++)
#pragma unroll
        for (int j = 0; j < 4; j++)
#pragma unroll
            for (int q = 0; q < 4; q++) acc[i][j][q] = 0.0f;

    load_stage(sm + 0 * STAGE_FLOATS, 0, bm, bn, tid);
    load_stage(sm + 1 * STAGE_FLOATS, 1, bm, bn, tid);
    load_stage(sm + 2 * STAGE_FLOATS, 2, bm, bn, tid);

    for (int kt = 0; kt < HDIM / 32; kt++) {
        CP_WAIT2();                      // stage kt resident
        __syncthreads();                 // all warps done with slot (kt-1)&3
        if (kt + 3 < HDIM / 32)
            load_stage(sm + ((kt + 3) & 3) * STAGE_FLOATS, kt + 3, bm, bn, tid);

        const float* As = sm + (kt & 3) * STAGE_FLOATS;
        const float* Bs = As + 128 * ASTR;
#pragma unroll
        for (int ks = 0; ks < 4; ks++) {
            const int k = ks * 8;
            float a[4][4], b[4][2];
#pragma unroll
            for (int mt = 0; mt < 4; mt++) {
                const float* ap = As + (warpM * 64 + mt * 16 + r) * ASTR + k + c;
                a[mt][0] = ap[0];
                a[mt][1] = ap[8 * ASTR];
                a[mt][2] = ap[4];
                a[mt][3] = ap[8 * ASTR + 4];
            }
#pragma unroll
            for (int nt = 0; nt < 4; nt++) {
                const float* bp = Bs + (warpN * 32 + nt * 8 + r) * ASTR + k + c;
                b[nt][0] = bp[0];
                b[nt][1] = bp[4];
            }
#pragma unroll
            for (int mt = 0; mt < 4; mt++)
#pragma unroll
                for (int nt = 0; nt < 4; nt++)
                    mma_tf32(acc[mt][nt], a[mt], b[nt]);
        }
    }

    // epilogue: bias + tanh + store
    const int row_base = bm * 128 + warpM * 64;
    const int col_base = bn * 128 + warpN * 32;
#pragma unroll
    for (int mt = 0; mt < 4; mt++) {
#pragma unroll
        for (int nt = 0; nt < 4; nt++) {
            int row = row_base + mt * 16 + r;
            int col = col_base + nt * 8 + c * 2;
            float bx = b2[col], by = b2[col + 1];
            float2 v0, v1;
            v0.x = tanhf(acc[mt][nt][0] + bx);
            v0.y = tanhf(acc[mt][nt][1] + by);
            v1.x = tanhf(acc[mt][nt][2] + bx);
            v1.y = tanhf(acc[mt][nt][3] + by);
            *reinterpret_cast<float2*>(&g_H2[(size_t)row * HDIM + col])       = v0;
            *reinterpret_cast<float2*>(&g_H2[(size_t)(row + 8) * HDIM + col]) = v1;
        }
    }
}

// ---------------------------------------------------------------------------
// Kernel 2: u = 3 * tanh(H2 @ W3 + b3)   (one warp per row)
// ---------------------------------------------------------------------------
__global__ void gemv_tanh_kernel(const float* __restrict__ W3,
                                 const float* __restrict__ b3) {
    int row  = blockIdx.x * 8 + (threadIdx.x >> 5);
    int lane = threadIdx.x & 31;
    const float4* r = reinterpret_cast<const float4*>(g_H2 + (size_t)row * HDIM);
    const float4* w = reinterpret_cast<const float4*>(W3);
    float s = 0.0f;
#pragma unroll 4
    for (int j = lane; j < HDIM / 4; j += 32) {
        float4 a = r[j], b = w[j];
        s += a.x * b.x + a.y * b.y + a.z * b.z + a.w * b.w;
    }
#pragma unroll
    for (int o = 16; o > 0; o >>= 1) s += __shfl_down_sync(0xffffffffu, s, o);
    if (lane == 0) g_u[row] = tanhf(s + b3[0]) * 3.0f;
}

// ---------------------------------------------------------------------------
// Kernel 3: spline evaluation over 2M points against 64x64 grid in SMEM
// ---------------------------------------------------------------------------
__global__ __launch_bounds__(256)
void spline_kernel(const float2* __restrict__ pts, float* __restrict__ out) {
    __shared__ float su[64 * 64];
    for (int i = threadIdx.x; i < 64 * 64; i += 256) su[i] = g_u[i];
    __syncthreads();

    for (int idx = blockIdx.x * blockDim.x + threadIdx.x; idx < NPTS;
         idx += gridDim.x * blockDim.x) {
        float2 p = pts[idx];
        float x = (p.x + 1.0f) * 0.5f;
        float y = p.y;

        float pfx = x * 62.0f;
        float flx = floorf(pfx);
        int   posx = min((int)flx + 1, 62);
        float tx = pfx - flx;
        float omtx = 1.0f - tx;
        float bx0 = 0.5f * omtx * omtx;
        float bx1 = -tx * tx + tx + 0.5f;
        float bx2 = 0.5f * tx * tx;

        float pfy = y * 62.0f;
        float fly = floorf(pfy);
        int   posy = min((int)fly + 1, 62);
        float ty = pfy - fly;
        float omty = 1.0f - ty;
        float by0 = 0.5f * omty * omty;
        float by1 = -ty * ty + ty + 0.5f;
        float by2 = 0.5f * ty * ty;

        const float* base = su + (posx - 1) * 64 + (posy - 1);
        float r0 = base[  0] * by0 + base[  1] * by1 + base[  2] * by2;
        float r1 = base[ 64] * by0 + base[ 65] * by1 + base[ 66] * by2;
        float r2 = base[128] * by0 + base[129] * by1 + base[130] * by2;
        out[idx] = r0 * bx0 + r1 * bx1 + r2 * bx2;
    }
}

// ---------------------------------------------------------------------------
// Launch
// ---------------------------------------------------------------------------
extern "C" void kernel_launch(void* const* d_in, const int* in_sizes, int n_in,
                              void* d_out, int out_size) {
    const float* points = (const float*)d_in[0];
    const float* W1     = (const float*)d_in[1];
    const float* b1     = (const float*)d_in[2];
    const float* W2     = (const float*)d_in[3];
    const float* b2     = (const float*)d_in[4];
    const float* W3     = (const float*)d_in[5];
    const float* b3     = (const float*)d_in[6];
    float* out = (float*)d_out;

    static int smem_set = 0;
    if (!smem_set) {
        cudaFuncSetAttribute(gemm_mma_kernel,
                             cudaFuncAttributeMaxDynamicSharedMemorySize, GEMM_SMEM);
        smem_set = 1;
    }

    // 0: A = tf32(tanh(W1 + b1))
    {
        int n4 = (IN_DIM * HDIM) / 4;
        prep_A_kernel<<<(n4 + 255) / 256, 256>>>(W1, b1);
    }
    // 0b: Bt = tf32(W2^T)
    {
        dim3 grid(HDIM / 32, HDIM / 32), blk(32, 8);
        transpose_kernel<<<grid, blk>>>(W2);
    }
    // 1: H2 = tanh(A @ W2 + b2)  (mma.sync tf32)
    {
        dim3 grid(HDIM / 128, IN_DIM / 128);
        gemm_mma_kernel<<<grid, 256, GEMM_SMEM>>>(b2);
    }
    // 2: u = 3 * tanh(H2 @ W3 + b3)
    gemv_tanh_kernel<<<IN_DIM / 8, 256>>>(W3, b3);
    // 3: spline
    spline_kernel<<<4096, 256>>>((const float2*)points, out);
}

// round 4
// speedup vs baseline: 5.0694x; 1.8811x over previous
#include <cuda_runtime.h>
#include <cuda_fp16.h>
#include <math.h>
#include <stdint.h>

#define IN_DIM 4096
#define HDIM   2048
#define NPTS   2097152

// Scratch (allocation-free): __device__ globals.
__device__ __half g_Ah [IN_DIM * HDIM];  // tanh(W1 + b1) in fp16      16 MB
__device__ __half g_Bth[HDIM * HDIM];    // W2^T in fp16 (N-major)      8 MB
__device__ float  g_H2 [IN_DIM * HDIM];  // tanh(A@W2 + b2)            32 MB
__device__ float  g_u  [IN_DIM];         // 3*tanh(H2@W3 + b3) (64x64)

#define CP_ASYNC16(dst, src) \
    asm volatile("cp.async.cg.shared.global [%0], [%1], 16;" \
                 :: "r"(dst), "l"(src) : "memory")
#define CP_COMMIT()  asm volatile("cp.async.commit_group;" ::: "memory")
#define CP_WAIT1()   asm volatile("cp.async.wait_group 1;" ::: "memory")

__device__ __forceinline__ void ldsm_x4(uint32_t* r, uint32_t addr) {
    asm volatile("ldmatrix.sync.aligned.m8n8.x4.shared.b16 {%0,%1,%2,%3}, [%4];"
                 : "=r"(r[0]), "=r"(r[1]), "=r"(r[2]), "=r"(r[3]) : "r"(addr));
}

__device__ __forceinline__ void mma_f16(float* d, const uint32_t* a, const uint32_t* b) {
    asm volatile(
        "mma.sync.aligned.m16n8k16.row.col.f32.f16.f16.f32 "
        "{%0,%1,%2,%3},{%4,%5,%6,%7},{%8,%9},{%0,%1,%2,%3};"
        : "+f"(d[0]), "+f"(d[1]), "+f"(d[2]), "+f"(d[3])
        : "r"(a[0]), "r"(a[1]), "r"(a[2]), "r"(a[3]), "r"(b[0]), "r"(b[1]));
}

// ---------------------------------------------------------------------------
// Kernel 0: Ah = half(tanh(W1 + b1))
// ---------------------------------------------------------------------------
__global__ void prep_A_kernel(const float* __restrict__ W1,
                              const float* __restrict__ b1) {
    int i = blockIdx.x * blockDim.x + threadIdx.x;     // float4 index
    if (i >= (IN_DIM * HDIM) / 4) return;
    float4 w = reinterpret_cast<const float4*>(W1)[i];
    float4 b = reinterpret_cast<const float4*>(b1)[i & (HDIM / 4 - 1)];
    __half2 h0 = __floats2half2_rn(tanhf(w.x + b.x), tanhf(w.y + b.y));
    __half2 h1 = __floats2half2_rn(tanhf(w.z + b.z), tanhf(w.w + b.w));
    uint2 v = make_uint2(*(uint32_t*)&h0, *(uint32_t*)&h1);
    reinterpret_cast<uint2*>(g_Ah)[i] = v;
}

// ---------------------------------------------------------------------------
// Kernel 0b: Bth[n][k] = half(W2[k][n])
// ---------------------------------------------------------------------------
__global__ void transpose_kernel(const float* __restrict__ W2) {
    __shared__ float t[32][33];
    int bx = blockIdx.x, by = blockIdx.y;
    int tx = threadIdx.x, ty = threadIdx.y;      // (32, 8)
#pragma unroll
    for (int i = 0; i < 32; i += 8)
        t[ty + i][tx] = W2[(size_t)(by * 32 + ty + i) * HDIM + bx * 32 + tx];
    __syncthreads();
#pragma unroll
    for (int i = 0; i < 32; i += 8)
        g_Bth[(size_t)(bx * 32 + ty + i) * HDIM + by * 32 + tx] =
            __float2half_rn(t[tx][ty + i]);
}

// ---------------------------------------------------------------------------
// Kernel 1: H2 = tanh(A @ W2 + b2)
//   mma.sync m16n8k16 f16->f32. CTA tile 128x256, BK=64 halves, 3-stage
//   cp.async. 8 warps (2M x 4N), warp tile 64x64 -> 4x8 mma tiles.
//   SMEM rows: 64 halves + 8 pad = 144B stride (ldmatrix conflict-free).
// ---------------------------------------------------------------------------
#define RSTR_B   144                           // bytes per smem row
#define A_TILE_B (128 * RSTR_B)                // 18432
#define B_TILE_B (256 * RSTR_B)                // 36864
#define STAGE_B  (A_TILE_B + B_TILE_B)         // 55296
#define NST      3
#define GEMM_SMEM (NST * STAGE_B)              // 165888

__device__ __forceinline__ void load_stage(uint32_t sbase, int kt,
                                           int bm, int bn, int tid) {
    uint32_t slot = sbase + (kt % NST) * STAGE_B;
    const int k0 = kt * 64;                    // halves
#pragma unroll
    for (int i = 0; i < 4; i++) {              // A: 1024 x 16B
        int g = i * 256 + tid;
        int row = g >> 3, c = g & 7;
        const __half* src = g_Ah + (size_t)(bm * 128 + row) * HDIM + k0 + c * 8;
        CP_ASYNC16(slot + row * RSTR_B + c * 16, src);
    }
#pragma unroll
    for (int i = 0; i < 8; i++) {              // B: 2048 x 16B
        int g = i * 256 + tid;
        int row = g >> 3, c = g & 7;
        const __half* src = g_Bth + (size_t)(bn * 256 + row) * HDIM + k0 + c * 8;
        CP_ASYNC16(slot + A_TILE_B + row * RSTR_B + c * 16, src);
    }
    CP_COMMIT();
}

__global__ __launch_bounds__(256, 1)
void gemm_mma_kernel(const float* __restrict__ b2) {
    extern __shared__ char smem[];
    const uint32_t sbase = (uint32_t)__cvta_generic_to_shared(smem);
    const int tid  = threadIdx.x;
    const int lane = tid & 31, wid = tid >> 5;
    const int warpM = wid & 1;                 // 0..1 -> 64 rows
    const int warpN = wid >> 1;                // 0..3 -> 64 cols
    const int bm = blockIdx.y, bn = blockIdx.x;

    // ldmatrix per-lane offsets (bytes within tile)
    const uint32_t aOff = (uint32_t)(warpM * 64 + (lane & 15)) * RSTR_B
                        + ((lane >> 4) & 1) * 16;
    const uint32_t bOff = A_TILE_B
                        + (uint32_t)(warpN * 64 + (lane & 7) + ((lane >> 4) << 3)) * RSTR_B
                        + ((lane >> 3) & 1) * 16;

    float acc[4][8][4];
#pragma unroll
    for (int i = 0; i < 4; i++)
#pragma unroll
        for (int j = 0; j < 8; j++)
#pragma unroll
            for (int q = 0; q < 4; q++) acc[i][j][q] = 0.0f;

    load_stage(sbase, 0, bm, bn, tid);
    load_stage(sbase, 1, bm, bn, tid);

    for (int kt = 0; kt < HDIM / 64; kt++) {
        CP_WAIT1();                             // stage kt resident
        __syncthreads();
        if (kt + 2 < HDIM / 64)
            load_stage(sbase, kt + 2, bm, bn, tid);

        const uint32_t slot = sbase + (kt % NST) * STAGE_B;
#pragma unroll
        for (int ks = 0; ks < 4; ks++) {        // 4 x k16
            uint32_t a[4][4], b[8][2];
#pragma unroll
            for (int mt = 0; mt < 4; mt++)
                ldsm_x4(a[mt], slot + aOff + mt * 16 * RSTR_B + ks * 32);
#pragma unroll
            for (int p = 0; p < 4; p++) {
                uint32_t r[4];
                ldsm_x4(r, slot + bOff + p * 16 * RSTR_B + ks * 32);
                b[2 * p][0] = r[0]; b[2 * p][1] = r[1];
                b[2 * p + 1][0] = r[2]; b[2 * p + 1][1] = r[3];
            }
#pragma unroll
            for (int mt = 0; mt < 4; mt++)
#pragma unroll
                for (int nt = 0; nt < 8; nt++)
                    mma_f16(acc[mt][nt], a[mt], b[nt]);
        }
    }

    // epilogue: bias + tanh + store fp32 H2
    const int r = lane >> 2, c = lane & 3;
    const int row_base = bm * 128 + warpM * 64;
    const int col_base = bn * 256 + warpN * 64;
#pragma unroll
    for (int mt = 0; mt < 4; mt++) {
#pragma unroll
        for (int nt = 0; nt < 8; nt++) {
            int row = row_base + mt * 16 + r;
            int col = col_base + nt * 8 + c * 2;
            float bx = b2[col], by = b2[col + 1];
            float2 v0, v1;
            v0.x = tanhf(acc[mt][nt][0] + bx);
            v0.y = tanhf(acc[mt][nt][1] + by);
            v1.x = tanhf(acc[mt][nt][2] + bx);
            v1.y = tanhf(acc[mt][nt][3] + by);
            *reinterpret_cast<float2*>(&g_H2[(size_t)row * HDIM + col])       = v0;
            *reinterpret_cast<float2*>(&g_H2[(size_t)(row + 8) * HDIM + col]) = v1;
        }
    }
}

// ---------------------------------------------------------------------------
// Kernel 2: u = 3 * tanh(H2 @ W3 + b3)   (one warp per row)
// ---------------------------------------------------------------------------
__global__ void gemv_tanh_kernel(const float* __restrict__ W3,
                                 const float* __restrict__ b3) {
    int row  = blockIdx.x * 8 + (threadIdx.x >> 5);
    int lane = threadIdx.x & 31;
    const float4* r = reinterpret_cast<const float4*>(g_H2 + (size_t)row * HDIM);
    const float4* w = reinterpret_cast<const float4*>(W3);
    float s = 0.0f;
#pragma unroll 4
    for (int j = lane; j < HDIM / 4; j += 32) {
        float4 a = r[j], b = w[j];
        s += a.x * b.x + a.y * b.y + a.z * b.z + a.w * b.w;
    }
#pragma unroll
    for (int o = 16; o > 0; o >>= 1) s += __shfl_down_sync(0xffffffffu, s, o);
    if (lane == 0) g_u[row] = tanhf(s + b3[0]) * 3.0f;
}

// ---------------------------------------------------------------------------
// Kernel 3: spline, 2 points per thread (float4 in, float2 out)
// ---------------------------------------------------------------------------
__device__ __forceinline__ float spline_eval(const float* su, float px, float py) {
    float pfx = ((px + 1.0f) * 0.5f) * 62.0f;
    float flx = floorf(pfx);
    int   posx = min((int)flx + 1, 62);
    float tx = pfx - flx, omtx = 1.0f - tx;
    float bx0 = 0.5f * omtx * omtx;
    float bx1 = -tx * tx + tx + 0.5f;
    float bx2 = 0.5f * tx * tx;

    float pfy = py * 62.0f;
    float fly = floorf(pfy);
    int   posy = min((int)fly + 1, 62);
    float ty = pfy - fly, omty = 1.0f - ty;
    float by0 = 0.5f * omty * omty;
    float by1 = -ty * ty + ty + 0.5f;
    float by2 = 0.5f * ty * ty;

    const float* base = su + (posx - 1) * 64 + (posy - 1);
    float r0 = base[  0] * by0 + base[  1] * by1 + base[  2] * by2;
    float r1 = base[ 64] * by0 + base[ 65] * by1 + base[ 66] * by2;
    float r2 = base[128] * by0 + base[129] * by1 + base[130] * by2;
    return r0 * bx0 + r1 * bx1 + r2 * bx2;
}

__global__ __launch_bounds__(256)
void spline_kernel(const float4* __restrict__ pts4, float2* __restrict__ out2) {
    __shared__ float su[64 * 64];
    for (int i = threadIdx.x; i < 64 * 64; i += 256) su[i] = g_u[i];
    __syncthreads();

    int idx = blockIdx.x * blockDim.x + threadIdx.x;      // pair index
    if (idx >= NPTS / 2) return;
    float4 p = pts4[idx];
    float2 o;
    o.x = spline_eval(su, p.x, p.y);
    o.y = spline_eval(su, p.z, p.w);
    out2[idx] = o;
}

// ---------------------------------------------------------------------------
// Launch
// ---------------------------------------------------------------------------
extern "C" void kernel_launch(void* const* d_in, const int* in_sizes, int n_in,
                              void* d_out, int out_size) {
    const float* points = (const float*)d_in[0];
    const float* W1     = (const float*)d_in[1];
    const float* b1     = (const float*)d_in[2];
    const float* W2     = (const float*)d_in[3];
    const float* b2     = (const float*)d_in[4];
    const float* W3     = (const float*)d_in[5];
    const float* b3     = (const float*)d_in[6];
    float* out = (float*)d_out;

    static int smem_set = 0;
    if (!smem_set) {
        cudaFuncSetAttribute(gemm_mma_kernel,
                             cudaFuncAttributeMaxDynamicSharedMemorySize, GEMM_SMEM);
        smem_set = 1;
    }

    // 0: Ah = half(tanh(W1 + b1))
    {
        int n4 = (IN_DIM * HDIM) / 4;
        prep_A_kernel<<<(n4 + 255) / 256, 256>>>(W1, b1);
    }
    // 0b: Bth = half(W2^T)
    {
        dim3 grid(HDIM / 32, HDIM / 32), blk(32, 8);
        transpose_kernel<<<grid, blk>>>(W2);
    }
    // 1: H2 = tanh(A @ W2 + b2)  (mma.sync f16)
    {
        dim3 grid(HDIM / 256, IN_DIM / 128);
        gemm_mma_kernel<<<grid, 256, GEMM_SMEM>>>(b2);
    }
    // 2: u = 3 * tanh(H2 @ W3 + b3)
    gemv_tanh_kernel<<<IN_DIM / 8, 256>>>(W3, b3);
    // 3: spline
    spline_kernel<<<NPTS / 512, 256>>>((const float4*)points, (float2*)out);
}

// round 5
// speedup vs baseline: 5.6265x; 1.1099x over previous
#include <cuda_runtime.h>
#include <cuda_fp16.h>
#include <math.h>
#include <stdint.h>

#define IN_DIM 4096
#define HDIM   2048
#define NPTS   2097152

// Scratch (allocation-free): __device__ globals.
__device__ __half g_Ah  [IN_DIM * HDIM];   // tanh(W1 + b1) fp16        16 MB
__device__ __half g_Bth [HDIM * HDIM];     // W2^T fp16 (N-major)        8 MB
__device__ float  g_part[IN_DIM * 64];     // partial gemv sums          1 MB
__device__ float  g_u   [IN_DIM];          // 3*tanh(out) (64x64 grid)

__device__ __forceinline__ float tanh_fast(float x) {
    // deg-7 odd Taylor; rel trunc err < 5e-6 for |x| <= 0.35
    float t = x * x;
    float p = fmaf(t, fmaf(t, fmaf(t, -0.05396825f, 0.13333334f), -0.33333334f), 1.0f);
    float r = x * p;
    if (fabsf(x) > 0.35f) r = tanhf(x);    // safety fallback (rarely taken)
    return r;
}

#define CP_ASYNC16(dst, src) \
    asm volatile("cp.async.cg.shared.global [%0], [%1], 16;" \
                 :: "r"(dst), "l"(src) : "memory")
#define CP_COMMIT()  asm volatile("cp.async.commit_group;" ::: "memory")
#define CP_WAIT1()   asm volatile("cp.async.wait_group 1;" ::: "memory")

__device__ __forceinline__ void ldsm_x4(uint32_t* r, uint32_t addr) {
    asm volatile("ldmatrix.sync.aligned.m8n8.x4.shared.b16 {%0,%1,%2,%3}, [%4];"
                 : "=r"(r[0]), "=r"(r[1]), "=r"(r[2]), "=r"(r[3]) : "r"(addr));
}

__device__ __forceinline__ void mma_f16(float* d, const uint32_t* a, const uint32_t* b) {
    asm volatile(
        "mma.sync.aligned.m16n8k16.row.col.f32.f16.f16.f32 "
        "{%0,%1,%2,%3},{%4,%5,%6,%7},{%8,%9},{%0,%1,%2,%3};"
        : "+f"(d[0]), "+f"(d[1]), "+f"(d[2]), "+f"(d[3])
        : "r"(a[0]), "r"(a[1]), "r"(a[2]), "r"(a[3]), "r"(b[0]), "r"(b[1]));
}

// ---------------------------------------------------------------------------
// Kernel 0: Ah = half(tanh(W1 + b1))
// ---------------------------------------------------------------------------
__global__ void prep_A_kernel(const float* __restrict__ W1,
                              const float* __restrict__ b1) {
    int i = blockIdx.x * blockDim.x + threadIdx.x;
    if (i >= (IN_DIM * HDIM) / 4) return;
    float4 w = reinterpret_cast<const float4*>(W1)[i];
    float4 b = reinterpret_cast<const float4*>(b1)[i & (HDIM / 4 - 1)];
    __half2 h0 = __floats2half2_rn(tanh_fast(w.x + b.x), tanh_fast(w.y + b.y));
    __half2 h1 = __floats2half2_rn(tanh_fast(w.z + b.z), tanh_fast(w.w + b.w));
    uint2 v = make_uint2(*(uint32_t*)&h0, *(uint32_t*)&h1);
    reinterpret_cast<uint2*>(g_Ah)[i] = v;
}

// ---------------------------------------------------------------------------
// Kernel 0b: Bth[n][k] = half(W2[k][n])
// ---------------------------------------------------------------------------
__global__ void transpose_kernel(const float* __restrict__ W2) {
    __shared__ float t[32][33];
    int bx = blockIdx.x, by = blockIdx.y;
    int tx = threadIdx.x, ty = threadIdx.y;      // (32, 8)
#pragma unroll
    for (int i = 0; i < 32; i += 8)
        t[ty + i][tx] = W2[(size_t)(by * 32 + ty + i) * HDIM + bx * 32 + tx];
    __syncthreads();
#pragma unroll
    for (int i = 0; i < 32; i += 8)
        g_Bth[(size_t)(bx * 32 + ty + i) * HDIM + by * 32 + tx] =
            __float2half_rn(t[tx][ty + i]);
}

// ---------------------------------------------------------------------------
// Kernel 1: fused  part[m, chunk] = sum_{cols in chunk} tanh(A@W2 + b2) * W3
//   mma.sync m16n8k16 f16->f32. CTA tile 128x128, BK=64 halves, 3-stage
//   cp.async, 2 CTAs/SM. 8 warps (2M x 4N), warp tile 64x32.
// ---------------------------------------------------------------------------
#define RSTR_B   144                           // bytes per smem row (64h + 8 pad)
#define A_TILE_B (128 * RSTR_B)                // 18432
#define STAGE_B  (2 * A_TILE_B)                // 36864
#define NST      3
#define GEMM_SMEM (NST * STAGE_B)              // 110592

__device__ __forceinline__ void load_stage(uint32_t sbase, int kt,
                                           int bm, int bn, int tid) {
    uint32_t slot = sbase + (kt % NST) * STAGE_B;
    const int k0 = kt * 64;
#pragma unroll
    for (int i = 0; i < 4; i++) {              // A: 1024 x 16B
        int g = i * 256 + tid;
        int row = g >> 3, c = g & 7;
        const __half* src = g_Ah + (size_t)(bm * 128 + row) * HDIM + k0 + c * 8;
        CP_ASYNC16(slot + row * RSTR_B + c * 16, src);
    }
#pragma unroll
    for (int i = 0; i < 4; i++) {              // B: 1024 x 16B
        int g = i * 256 + tid;
        int row = g >> 3, c = g & 7;
        const __half* src = g_Bth + (size_t)(bn * 128 + row) * HDIM + k0 + c * 8;
        CP_ASYNC16(slot + A_TILE_B + row * RSTR_B + c * 16, src);
    }
    CP_COMMIT();
}

__global__ __launch_bounds__(256, 2)
void gemm_mma_kernel(const float* __restrict__ b2, const float* __restrict__ W3) {
    extern __shared__ char smem[];
    const uint32_t sbase = (uint32_t)__cvta_generic_to_shared(smem);
    const int tid  = threadIdx.x;
    const int lane = tid & 31, wid = tid >> 5;
    const int warpM = wid & 1;                 // 0..1 -> 64 rows
    const int warpN = wid >> 1;                // 0..3 -> 32 cols
    const int bm = blockIdx.y, bn = blockIdx.x;

    const uint32_t aOff = (uint32_t)(warpM * 64 + (lane & 15)) * RSTR_B
                        + ((lane >> 4) & 1) * 16;
    const uint32_t bOff = A_TILE_B
                        + (uint32_t)(warpN * 32 + (lane & 7) + ((lane >> 4) << 3)) * RSTR_B
                        + ((lane >> 3) & 1) * 16;

    float acc[4][4][4];
#pragma unroll
    for (int i = 0; i < 4; i++)
#pragma unroll
        for (int j = 0; j < 4; j++)
#pragma unroll
            for (int q = 0; q < 4; q++) acc[i][j][q] = 0.0f;

    load_stage(sbase, 0, bm, bn, tid);
    load_stage(sbase, 1, bm, bn, tid);

    for (int kt = 0; kt < HDIM / 64; kt++) {
        CP_WAIT1();                             // stage kt resident
        __syncthreads();                        // all warps done with slot kt-1
        if (kt + 2 < HDIM / 64)
            load_stage(sbase, kt + 2, bm, bn, tid);

        const uint32_t slot = sbase + (kt % NST) * STAGE_B;
#pragma unroll
        for (int ks = 0; ks < 4; ks++) {        // 4 x k16
            uint32_t a[4][4], b[4][2];
#pragma unroll
            for (int mt = 0; mt < 4; mt++)
                ldsm_x4(a[mt], slot + aOff + mt * 16 * RSTR_B + ks * 32);
#pragma unroll
            for (int p = 0; p < 2; p++) {
                uint32_t r[4];
                ldsm_x4(r, slot + bOff + p * 16 * RSTR_B + ks * 32);
                b[2 * p][0] = r[0]; b[2 * p][1] = r[1];
                b[2 * p + 1][0] = r[2]; b[2 * p + 1][1] = r[3];
            }
#pragma unroll
            for (int mt = 0; mt < 4; mt++)
#pragma unroll
                for (int nt = 0; nt < 4; nt++)
                    mma_f16(acc[mt][nt], a[mt], b[nt]);
        }
    }

    // fused epilogue: bias + tanh + dot with W3, reduce over lanes, store partials
    const int r = lane >> 2, c = lane & 3;
    const int col_base = bn * 128 + warpN * 32;
    float w3v[8], b2v[8];
#pragma unroll
    for (int nt = 0; nt < 4; nt++) {
        int col = col_base + nt * 8 + c * 2;
        w3v[2 * nt]     = W3[col];
        w3v[2 * nt + 1] = W3[col + 1];
        b2v[2 * nt]     = b2[col];
        b2v[2 * nt + 1] = b2[col + 1];
    }
    const int row_base = bm * 128 + warpM * 64;
    const int chunk = bn * 4 + warpN;           // 0..63
#pragma unroll
    for (int mt = 0; mt < 4; mt++) {
        float s0 = 0.0f, s1 = 0.0f;
#pragma unroll
        for (int nt = 0; nt < 4; nt++) {
            s0 += tanh_fast(acc[mt][nt][0] + b2v[2 * nt]) * w3v[2 * nt]
                + tanh_fast(acc[mt][nt][1] + b2v[2 * nt + 1]) * w3v[2 * nt + 1];
            s1 += tanh_fast(acc[mt][nt][2] + b2v[2 * nt]) * w3v[2 * nt]
                + tanh_fast(acc[mt][nt][3] + b2v[2 * nt + 1]) * w3v[2 * nt + 1];
        }
        // reduce over the 4 lanes sharing row r
        s0 += __shfl_xor_sync(0xffffffffu, s0, 1);
        s0 += __shfl_xor_sync(0xffffffffu, s0, 2);
        s1 += __shfl_xor_sync(0xffffffffu, s1, 1);
        s1 += __shfl_xor_sync(0xffffffffu, s1, 2);
        if (c == 0) {
            int row = row_base + mt * 16 + r;
            g_part[(size_t)row * 64 + chunk]       = s0;
            g_part[(size_t)(row + 8) * 64 + chunk] = s1;
        }
    }
}

// ---------------------------------------------------------------------------
// Kernel 2: u[row] = 3 * tanh(sum_chunk part[row,chunk] + b3)
// ---------------------------------------------------------------------------
__global__ void reduce_u_kernel(const float* __restrict__ b3) {
    int row = blockIdx.x * blockDim.x + threadIdx.x;
    if (row >= IN_DIM) return;
    const float4* p = reinterpret_cast<const float4*>(g_part + (size_t)row * 64);
    float s = 0.0f;
#pragma unroll
    for (int j = 0; j < 16; j++) {
        float4 v = p[j];
        s += (v.x + v.y) + (v.z + v.w);
    }
    g_u[row] = 3.0f * tanh_fast(s + b3[0]);
}

// ---------------------------------------------------------------------------
// Kernel 3: spline, 4 points per thread
// ---------------------------------------------------------------------------
__device__ __forceinline__ float spline_eval(const float* su, float px, float py) {
    float pfx = ((px + 1.0f) * 0.5f) * 62.0f;
    float flx = floorf(pfx);
    int   posx = min((int)flx + 1, 62);
    float tx = pfx - flx, omtx = 1.0f - tx;
    float bx0 = 0.5f * omtx * omtx;
    float bx1 = -tx * tx + tx + 0.5f;
    float bx2 = 0.5f * tx * tx;

    float pfy = py * 62.0f;
    float fly = floorf(pfy);
    int   posy = min((int)fly + 1, 62);
    float ty = pfy - fly, omty = 1.0f - ty;
    float by0 = 0.5f * omty * omty;
    float by1 = -ty * ty + ty + 0.5f;
    float by2 = 0.5f * ty * ty;

    const float* base = su + (posx - 1) * 64 + (posy - 1);
    float r0 = base[  0] * by0 + base[  1] * by1 + base[  2] * by2;
    float r1 = base[ 64] * by0 + base[ 65] * by1 + base[ 66] * by2;
    float r2 = base[128] * by0 + base[129] * by1 + base[130] * by2;
    return r0 * bx0 + r1 * bx1 + r2 * bx2;
}

__global__ __launch_bounds__(256)
void spline_kernel(const float4* __restrict__ pts4, float4* __restrict__ out4) {
    __shared__ float su[64 * 64];
    for (int i = threadIdx.x; i < 64 * 64; i += 256) su[i] = g_u[i];
    __syncthreads();

    int idx = blockIdx.x * blockDim.x + threadIdx.x;      // quad index
    if (idx >= NPTS / 4) return;
    float4 p0 = pts4[2 * idx];
    float4 p1 = pts4[2 * idx + 1];
    float4 o;
    o.x = spline_eval(su, p0.x, p0.y);
    o.y = spline_eval(su, p0.z, p0.w);
    o.z = spline_eval(su, p1.x, p1.y);
    o.w = spline_eval(su, p1.z, p1.w);
    out4[idx] = o;
}

// ---------------------------------------------------------------------------
// Launch
// ---------------------------------------------------------------------------
extern "C" void kernel_launch(void* const* d_in, const int* in_sizes, int n_in,
                              void* d_out, int out_size) {
    const float* points = (const float*)d_in[0];
    const float* W1     = (const float*)d_in[1];
    const float* b1     = (const float*)d_in[2];
    const float* W2     = (const float*)d_in[3];
    const float* b2     = (const float*)d_in[4];
    const float* W3     = (const float*)d_in[5];
    const float* b3     = (const float*)d_in[6];
    float* out = (float*)d_out;

    static int smem_set = 0;
    if (!smem_set) {
        cudaFuncSetAttribute(gemm_mma_kernel,
                             cudaFuncAttributeMaxDynamicSharedMemorySize, GEMM_SMEM);
        smem_set = 1;
    }

    // 0: Ah = half(tanh(W1 + b1))
    {
        int n4 = (IN_DIM * HDIM) / 4;
        prep_A_kernel<<<(n4 + 255) / 256, 256>>>(W1, b1);
    }
    // 0b: Bth = half(W2^T)
    {
        dim3 grid(HDIM / 32, HDIM / 32), blk(32, 8);
        transpose_kernel<<<grid, blk>>>(W2);
    }
    // 1: fused GEMM + tanh + partial GEMV
    {
        dim3 grid(HDIM / 128, IN_DIM / 128);
        gemm_mma_kernel<<<grid, 256, GEMM_SMEM>>>(b2, W3);
    }
    // 2: u = 3 * tanh(sum + b3)
    reduce_u_kernel<<<IN_DIM / 256, 256>>>(b3);
    // 3: spline
    spline_kernel<<<NPTS / 1024, 256>>>((const float4*)points, (float4*)out);
}

// round 6
// speedup vs baseline: 5.7022x; 1.0134x over previous
#include <cuda_runtime.h>
#include <cuda_fp16.h>
#include <math.h>
#include <stdint.h>

#define IN_DIM 4096
#define HDIM   2048
#define NPTS   2097152

// Scratch (allocation-free): __device__ globals.
__device__ __half g_Ah  [IN_DIM * HDIM];   // tanh(W1 + b1) fp16        16 MB
__device__ __half g_Bth [HDIM * HDIM];     // W2^T fp16 (N-major)        8 MB
__device__ float  g_part[IN_DIM * 64];     // partial gemv sums          1 MB
__device__ float  g_u   [IN_DIM];          // 3*tanh(out) (64x64 grid)

__device__ __forceinline__ float tanh_fast(float x) {
    // deg-7 odd Taylor; rel trunc err < 5e-6 for |x| <= 0.35
    float t = x * x;
    float p = fmaf(t, fmaf(t, fmaf(t, -0.05396825f, 0.13333334f), -0.33333334f), 1.0f);
    float r = x * p;
    if (fabsf(x) > 0.35f) r = tanhf(x);    // safety fallback (rarely taken)
    return r;
}

#define CP_ASYNC16(dst, src) \
    asm volatile("cp.async.cg.shared.global [%0], [%1], 16;" \
                 :: "r"(dst), "l"(src) : "memory")
#define CP_COMMIT()  asm volatile("cp.async.commit_group;" ::: "memory")
#define CP_WAIT1()   asm volatile("cp.async.wait_group 1;" ::: "memory")

__device__ __forceinline__ void ldsm_x4(uint32_t* r, uint32_t addr) {
    asm volatile("ldmatrix.sync.aligned.m8n8.x4.shared.b16 {%0,%1,%2,%3}, [%4];"
                 : "=r"(r[0]), "=r"(r[1]), "=r"(r[2]), "=r"(r[3]) : "r"(addr));
}

__device__ __forceinline__ void mma_f16(float* d, const uint32_t* a, const uint32_t* b) {
    asm volatile(
        "mma.sync.aligned.m16n8k16.row.col.f32.f16.f16.f32 "
        "{%0,%1,%2,%3},{%4,%5,%6,%7},{%8,%9},{%0,%1,%2,%3};"
        : "+f"(d[0]), "+f"(d[1]), "+f"(d[2]), "+f"(d[3])
        : "r"(a[0]), "r"(a[1]), "r"(a[2]), "r"(a[3]), "r"(b[0]), "r"(b[1]));
}

// packed f32x2 helpers (sm_103a)
__device__ __forceinline__ uint64_t pk2(float lo, float hi) {
    uint64_t r;
    asm("mov.b64 %0, {%1, %2};" : "=l"(r) : "f"(lo), "f"(hi));
    return r;
}
__device__ __forceinline__ void upk2(float& lo, float& hi, uint64_t v) {
    asm("mov.b64 {%0, %1}, %2;" : "=f"(lo), "=f"(hi) : "l"(v));
}
#define FMA2(d, a, b, c) \
    asm("fma.rn.f32x2 %0, %1, %2, %3;" : "=l"(d) : "l"(a), "l"(b), "l"(c))
#define MUL2(d, a, b) \
    asm("mul.rn.f32x2 %0, %1, %2;" : "=l"(d) : "l"(a), "l"(b))
#define ADD2(d, a, b) \
    asm("add.rn.f32x2 %0, %1, %2;" : "=l"(d) : "l"(a), "l"(b))

// ---------------------------------------------------------------------------
// Kernel 0: Ah = half(tanh(W1 + b1))
// ---------------------------------------------------------------------------
__global__ void prep_A_kernel(const float* __restrict__ W1,
                              const float* __restrict__ b1) {
    int i = blockIdx.x * blockDim.x + threadIdx.x;
    if (i >= (IN_DIM * HDIM) / 4) return;
    float4 w = reinterpret_cast<const float4*>(W1)[i];
    float4 b = reinterpret_cast<const float4*>(b1)[i & (HDIM / 4 - 1)];
    __half2 h0 = __floats2half2_rn(tanh_fast(w.x + b.x), tanh_fast(w.y + b.y));
    __half2 h1 = __floats2half2_rn(tanh_fast(w.z + b.z), tanh_fast(w.w + b.w));
    uint2 v = make_uint2(*(uint32_t*)&h0, *(uint32_t*)&h1);
    reinterpret_cast<uint2*>(g_Ah)[i] = v;
}

// ---------------------------------------------------------------------------
// Kernel 0b: Bth[n][k] = half(W2[k][n])
// ---------------------------------------------------------------------------
__global__ void transpose_kernel(const float* __restrict__ W2) {
    __shared__ float t[32][33];
    int bx = blockIdx.x, by = blockIdx.y;
    int tx = threadIdx.x, ty = threadIdx.y;      // (32, 8)
#pragma unroll
    for (int i = 0; i < 32; i += 8)
        t[ty + i][tx] = W2[(size_t)(by * 32 + ty + i) * HDIM + bx * 32 + tx];
    __syncthreads();
#pragma unroll
    for (int i = 0; i < 32; i += 8)
        g_Bth[(size_t)(bx * 32 + ty + i) * HDIM + by * 32 + tx] =
            __float2half_rn(t[tx][ty + i]);
}

// ---------------------------------------------------------------------------
// Kernel 1: fused  part[m, chunk] = sum_{cols in chunk} tanh(A@W2 + b2) * W3
//   mma.sync m16n8k16 f16->f32. CTA tile 128x128, BK=64 halves, 3-stage
//   cp.async, 2 CTAs/SM. 8 warps (2M x 4N), warp tile 64x32.
// ---------------------------------------------------------------------------
#define RSTR_B   144                           // bytes per smem row (64h + 8 pad)
#define A_TILE_B (128 * RSTR_B)                // 18432
#define STAGE_B  (2 * A_TILE_B)                // 36864
#define NST      3
#define GEMM_SMEM (NST * STAGE_B)              // 110592

__device__ __forceinline__ void load_stage(uint32_t sbase, int kt,
                                           int bm, int bn, int tid) {
    uint32_t slot = sbase + (kt % NST) * STAGE_B;
    const int k0 = kt * 64;
#pragma unroll
    for (int i = 0; i < 4; i++) {              // A: 1024 x 16B
        int g = i * 256 + tid;
        int row = g >> 3, c = g & 7;
        const __half* src = g_Ah + (size_t)(bm * 128 + row) * HDIM + k0 + c * 8;
        CP_ASYNC16(slot + row * RSTR_B + c * 16, src);
    }
#pragma unroll
    for (int i = 0; i < 4; i++) {              // B: 1024 x 16B
        int g = i * 256 + tid;
        int row = g >> 3, c = g & 7;
        const __half* src = g_Bth + (size_t)(bn * 128 + row) * HDIM + k0 + c * 8;
        CP_ASYNC16(slot + A_TILE_B + row * RSTR_B + c * 16, src);
    }
    CP_COMMIT();
}

__global__ __launch_bounds__(256, 2)
void gemm_mma_kernel(const float* __restrict__ b2, const float* __restrict__ W3) {
    extern __shared__ char smem[];
    const uint32_t sbase = (uint32_t)__cvta_generic_to_shared(smem);
    const int tid  = threadIdx.x;
    const int lane = tid & 31, wid = tid >> 5;
    const int warpM = wid & 1;                 // 0..1 -> 64 rows
    const int warpN = wid >> 1;                // 0..3 -> 32 cols
    const int bm = blockIdx.y, bn = blockIdx.x;

    const uint32_t aOff = (uint32_t)(warpM * 64 + (lane & 15)) * RSTR_B
                        + ((lane >> 4) & 1) * 16;
    const uint32_t bOff = A_TILE_B
                        + (uint32_t)(warpN * 32 + (lane & 7) + ((lane >> 4) << 3)) * RSTR_B
                        + ((lane >> 3) & 1) * 16;

    float acc[4][4][4];
#pragma unroll
    for (int i = 0; i < 4; i++)
#pragma unroll
        for (int j = 0; j < 4; j++)
#pragma unroll
            for (int q = 0; q < 4; q++) acc[i][j][q] = 0.0f;

    load_stage(sbase, 0, bm, bn, tid);
    load_stage(sbase, 1, bm, bn, tid);

    for (int kt = 0; kt < HDIM / 64; kt++) {
        CP_WAIT1();                             // stage kt resident
        __syncthreads();                        // all warps done with slot kt-1
        if (kt + 2 < HDIM / 64)
            load_stage(sbase, kt + 2, bm, bn, tid);

        const uint32_t slot = sbase + (kt % NST) * STAGE_B;
#pragma unroll
        for (int ks = 0; ks < 4; ks++) {        // 4 x k16
            uint32_t a[4][4], b[4][2];
#pragma unroll
            for (int mt = 0; mt < 4; mt++)
                ldsm_x4(a[mt], slot + aOff + mt * 16 * RSTR_B + ks * 32);
#pragma unroll
            for (int p = 0; p < 2; p++) {
                uint32_t r[4];
                ldsm_x4(r, slot + bOff + p * 16 * RSTR_B + ks * 32);
                b[2 * p][0] = r[0]; b[2 * p][1] = r[1];
                b[2 * p + 1][0] = r[2]; b[2 * p + 1][1] = r[3];
            }
#pragma unroll
            for (int mt = 0; mt < 4; mt++)
#pragma unroll
                for (int nt = 0; nt < 4; nt++)
                    mma_f16(acc[mt][nt], a[mt], b[nt]);
        }
    }

    // fused epilogue: bias + tanh + dot with W3, reduce over lanes, store partials
    const int r = lane >> 2, c = lane & 3;
    const int col_base = bn * 128 + warpN * 32;
    float w3v[8], b2v[8];
#pragma unroll
    for (int nt = 0; nt < 4; nt++) {
        int col = col_base + nt * 8 + c * 2;
        w3v[2 * nt]     = W3[col];
        w3v[2 * nt + 1] = W3[col + 1];
        b2v[2 * nt]     = b2[col];
        b2v[2 * nt + 1] = b2[col + 1];
    }
    const int row_base = bm * 128 + warpM * 64;
    const int chunk = bn * 4 + warpN;           // 0..63
#pragma unroll
    for (int mt = 0; mt < 4; mt++) {
        float s0 = 0.0f, s1 = 0.0f;
#pragma unroll
        for (int nt = 0; nt < 4; nt++) {
            s0 += tanh_fast(acc[mt][nt][0] + b2v[2 * nt]) * w3v[2 * nt]
                + tanh_fast(acc[mt][nt][1] + b2v[2 * nt + 1]) * w3v[2 * nt + 1];
            s1 += tanh_fast(acc[mt][nt][2] + b2v[2 * nt]) * w3v[2 * nt]
                + tanh_fast(acc[mt][nt][3] + b2v[2 * nt + 1]) * w3v[2 * nt + 1];
        }
        s0 += __shfl_xor_sync(0xffffffffu, s0, 1);
        s0 += __shfl_xor_sync(0xffffffffu, s0, 2);
        s1 += __shfl_xor_sync(0xffffffffu, s1, 1);
        s1 += __shfl_xor_sync(0xffffffffu, s1, 2);
        if (c == 0) {
            int row = row_base + mt * 16 + r;
            g_part[(size_t)row * 64 + chunk]       = s0;
            g_part[(size_t)(row + 8) * 64 + chunk] = s1;
        }
    }
}

// ---------------------------------------------------------------------------
// Kernel 2: u[row] = 3 * tanh(sum_chunk part[row,chunk] + b3)
//   warp-per-row: 4096 warps -> 512 blocks, fills the chip.
// ---------------------------------------------------------------------------
__global__ void reduce_u_kernel(const float* __restrict__ b3) {
    int row  = blockIdx.x * 8 + (threadIdx.x >> 5);
    int lane = threadIdx.x & 31;
    float2 v = reinterpret_cast<const float2*>(g_part + (size_t)row * 64)[lane];
    float s = v.x + v.y;
#pragma unroll
    for (int o = 16; o > 0; o >>= 1) s += __shfl_xor_sync(0xffffffffu, s, o);
    if (lane == 0) g_u[row] = 3.0f * tanh_fast(s + b3[0]);
}

// ---------------------------------------------------------------------------
// Kernel 3: spline, 4 points per thread, packed f32x2 weight math
// ---------------------------------------------------------------------------
__device__ __forceinline__ float spline_eval(const float* su, float px, float py) {
    const uint64_t C_scale = pk2(31.0f, 62.0f);
    const uint64_t C_off   = pk2(31.0f, 0.0f);
    const uint64_t C_half  = pk2(0.5f, 0.5f);
    const uint64_t C_neg1  = pk2(-1.0f, -1.0f);

    uint64_t P = pk2(px, py);
    uint64_t pf;
    FMA2(pf, P, C_scale, C_off);               // {(px+1)*31, py*62}
    float fx, fy;
    upk2(fx, fy, pf);
    float flx = floorf(fx), fly = floorf(fy);
    int posx = min((int)flx + 1, 62);
    int posy = min((int)fly + 1, 62);

    uint64_t fl = pk2(flx, fly);
    uint64_t t;
    FMA2(t, fl, C_neg1, pf);                   // t = pf - floor(pf)
    uint64_t t2, h, u0, b0, tp, b1;
    MUL2(t2, t, t);
    MUL2(h, t2, C_half);                       // 0.5 t^2  (= b2)
    ADD2(u0, h, C_half);
    FMA2(b0, t, C_neg1, u0);                   // 0.5 t^2 - t + 0.5
    ADD2(tp, t, C_half);
    FMA2(b1, t2, C_neg1, tp);                  // -t^2 + t + 0.5

    float bx0, by0, bx1, by1, bx2, by2;
    upk2(bx0, by0, b0);
    upk2(bx1, by1, b1);
    upk2(bx2, by2, h);

    const float* base = su + (posx - 1) * 64 + (posy - 1);
    float r0 = base[  0] * by0 + base[  1] * by1 + base[  2] * by2;
    float r1 = base[ 64] * by0 + base[ 65] * by1 + base[ 66] * by2;
    float r2 = base[128] * by0 + base[129] * by1 + base[130] * by2;
    return r0 * bx0 + r1 * bx1 + r2 * bx2;
}

__global__ __launch_bounds__(256)
void spline_kernel(const float4* __restrict__ pts4, float4* __restrict__ out4) {
    __shared__ float su[64 * 64];
    for (int i = threadIdx.x; i < 64 * 64; i += 256) su[i] = g_u[i];
    __syncthreads();

    int idx = blockIdx.x * blockDim.x + threadIdx.x;      // quad index
    if (idx >= NPTS / 4) return;
    float4 p0 = pts4[2 * idx];
    float4 p1 = pts4[2 * idx + 1];
    float4 o;
    o.x = spline_eval(su, p0.x, p0.y);
    o.y = spline_eval(su, p0.z, p0.w);
    o.z = spline_eval(su, p1.x, p1.y);
    o.w = spline_eval(su, p1.z, p1.w);
    out4[idx] = o;
}

// ---------------------------------------------------------------------------
// Launch
// ---------------------------------------------------------------------------
extern "C" void kernel_launch(void* const* d_in, const int* in_sizes, int n_in,
                              void* d_out, int out_size) {
    const float* points = (const float*)d_in[0];
    const float* W1     = (const float*)d_in[1];
    const float* b1     = (const float*)d_in[2];
    const float* W2     = (const float*)d_in[3];
    const float* b2     = (const float*)d_in[4];
    const float* W3     = (const float*)d_in[5];
    const float* b3     = (const float*)d_in[6];
    float* out = (float*)d_out;

    static int smem_set = 0;
    if (!smem_set) {
        cudaFuncSetAttribute(gemm_mma_kernel,
                             cudaFuncAttributeMaxDynamicSharedMemorySize, GEMM_SMEM);
        smem_set = 1;
    }

    // 0: Ah = half(tanh(W1 + b1))
    {
        int n4 = (IN_DIM * HDIM) / 4;
        prep_A_kernel<<<(n4 + 255) / 256, 256>>>(W1, b1);
    }
    // 0b: Bth = half(W2^T)
    {
        dim3 grid(HDIM / 32, HDIM / 32), blk(32, 8);
        transpose_kernel<<<grid, blk>>>(W2);
    }
    // 1: fused GEMM + tanh + partial GEMV
    {
        dim3 grid(HDIM / 128, IN_DIM / 128);
        gemm_mma_kernel<<<grid, 256, GEMM_SMEM>>>(b2, W3);
    }
    // 2: u = 3 * tanh(sum + b3)
    reduce_u_kernel<<<IN_DIM / 8, 256>>>(b3);
    // 3: spline
    spline_kernel<<<NPTS / 1024, 256>>>((const float4*)points, (float4*)out);
}